// round 15
// baseline (speedup 1.0000x reference)
#include <cuda_runtime.h>

#define BATCH 4096
#define DIM   4096
#define MARGIN 0.5f
#define WARPS_PER_CTA 8
#define GRID (BATCH / WARPS_PER_CTA)   // 512 CTAs x 8 warps = 4096 warps (one per row)

// scratch for per-row hinge losses (allocation-free rule: __device__ global)
__device__ float g_partial[BATCH];

// ---------------------------------------------------------------------------
// Kernel 1: ONE WARP PER ROW. Zero __syncthreads, zero smem, no t0
// serialization: each warp loads its row triplet lane-striped (coalesced
// 512B segments), shfl-reduces, lane 0 computes the hinge and stores stcg.
// Unroll-by-4 keeps 12 independent float4 loads in flight per thread.
// ---------------------------------------------------------------------------
__global__ __launch_bounds__(256)
void triplet_rows_kernel(const float* __restrict__ f,
                         const float* __restrict__ label,
                         const int*   __restrict__ idx1,
                         const int*   __restrict__ idx2)
{
    const int wid = threadIdx.x >> 5;
    const int lid = threadIdx.x & 31;
    const int i   = blockIdx.x * WARPS_PER_CTA + wid;   // row for this warp

    const int j1 = __ldg(&idx1[i]);
    const int j2 = __ldg(&idx2[i]);

    const float4* __restrict__ a  = (const float4*)(f + (size_t)i  * DIM);
    const float4* __restrict__ b1 = (const float4*)(f + (size_t)j1 * DIM);
    const float4* __restrict__ b2 = (const float4*)(f + (size_t)j2 * DIM);

    float s1 = 0.0f, s2 = 0.0f;

    // 1024 float4 per row / 32 lanes = 32 per lane; process 4 per batch
    // -> 12 independent loads in flight per thread.
    #pragma unroll
    for (int kk = 0; kk < 8; kk++) {
        const int base = lid + kk * 128;
        const float4 A0 = __ldg(&a[base]);
        const float4 A1 = __ldg(&a[base + 32]);
        const float4 A2 = __ldg(&a[base + 64]);
        const float4 A3 = __ldg(&a[base + 96]);
        const float4 P0 = __ldg(&b1[base]);
        const float4 P1 = __ldg(&b1[base + 32]);
        const float4 P2 = __ldg(&b1[base + 64]);
        const float4 P3 = __ldg(&b1[base + 96]);
        const float4 Q0 = __ldg(&b2[base]);
        const float4 Q1 = __ldg(&b2[base + 32]);
        const float4 Q2 = __ldg(&b2[base + 64]);
        const float4 Q3 = __ldg(&b2[base + 96]);

        float d;
        d = A0.x - P0.x; s1 = fmaf(d, d, s1);
        d = A0.y - P0.y; s1 = fmaf(d, d, s1);
        d = A0.z - P0.z; s1 = fmaf(d, d, s1);
        d = A0.w - P0.w; s1 = fmaf(d, d, s1);
        d = A1.x - P1.x; s1 = fmaf(d, d, s1);
        d = A1.y - P1.y; s1 = fmaf(d, d, s1);
        d = A1.z - P1.z; s1 = fmaf(d, d, s1);
        d = A1.w - P1.w; s1 = fmaf(d, d, s1);
        d = A2.x - P2.x; s1 = fmaf(d, d, s1);
        d = A2.y - P2.y; s1 = fmaf(d, d, s1);
        d = A2.z - P2.z; s1 = fmaf(d, d, s1);
        d = A2.w - P2.w; s1 = fmaf(d, d, s1);
        d = A3.x - P3.x; s1 = fmaf(d, d, s1);
        d = A3.y - P3.y; s1 = fmaf(d, d, s1);
        d = A3.z - P3.z; s1 = fmaf(d, d, s1);
        d = A3.w - P3.w; s1 = fmaf(d, d, s1);

        d = A0.x - Q0.x; s2 = fmaf(d, d, s2);
        d = A0.y - Q0.y; s2 = fmaf(d, d, s2);
        d = A0.z - Q0.z; s2 = fmaf(d, d, s2);
        d = A0.w - Q0.w; s2 = fmaf(d, d, s2);
        d = A1.x - Q1.x; s2 = fmaf(d, d, s2);
        d = A1.y - Q1.y; s2 = fmaf(d, d, s2);
        d = A1.z - Q1.z; s2 = fmaf(d, d, s2);
        d = A1.w - Q1.w; s2 = fmaf(d, d, s2);
        d = A2.x - Q2.x; s2 = fmaf(d, d, s2);
        d = A2.y - Q2.y; s2 = fmaf(d, d, s2);
        d = A2.z - Q2.z; s2 = fmaf(d, d, s2);
        d = A2.w - Q2.w; s2 = fmaf(d, d, s2);
        d = A3.x - Q3.x; s2 = fmaf(d, d, s2);
        d = A3.y - Q3.y; s2 = fmaf(d, d, s2);
        d = A3.z - Q3.z; s2 = fmaf(d, d, s2);
        d = A3.w - Q3.w; s2 = fmaf(d, d, s2);
    }

    // warp-only reduction, no smem, no barriers
    #pragma unroll
    for (int off = 16; off > 0; off >>= 1) {
        s1 += __shfl_down_sync(0xFFFFFFFFu, s1, off);
        s2 += __shfl_down_sync(0xFFFFFFFFu, s2, off);
    }

    if (lid == 0) {
        const float l  = __ldg(&label[i]);
        const float l1 = __ldg(&label[j1]);
        const float l2 = __ldg(&label[j2]);
        const float d1 = fabsf(l - l1);
        const float d2 = fabsf(l - l2);
        const bool cond = (d1 >= d2);       // true -> idx2 is the near sample

        const float a2n    = cond ? s2 : s1;
        const float a2f    = cond ? s1 : s2;
        const float near_l = cond ? l2 : l1;
        const float far_l  = cond ? l1 : l2;

        const float dn = l - near_l;
        const float df = l - far_l;
        const float alpha = df * df - dn * dn;
        __stcg(&g_partial[i], fmaxf(a2n - a2f + alpha * MARGIN, 0.0f));
    }

    // Dependent reduce may start launching; its wait blocks until this grid
    // fully completes + flushes.
    asm volatile("griddepcontrol.launch_dependents;");
}

// ---------------------------------------------------------------------------
// Kernel 2: PDL-launched reduce (unchanged, proven). Deterministic
// fixed-order sum of 4096 partials via L2.
// ---------------------------------------------------------------------------
__global__ __launch_bounds__(128, 1)
void reduce_kernel(float* __restrict__ out)
{
    asm volatile("griddepcontrol.wait;");

    const int t = threadIdx.x;
    const float4* p = (const float4*)g_partial;  // 1024 float4

    const float4 v0 = __ldcg(&p[t]);
    const float4 v1 = __ldcg(&p[t + 128]);
    const float4 v2 = __ldcg(&p[t + 256]);
    const float4 v3 = __ldcg(&p[t + 384]);
    const float4 v4 = __ldcg(&p[t + 512]);
    const float4 v5 = __ldcg(&p[t + 640]);
    const float4 v6 = __ldcg(&p[t + 768]);
    const float4 v7 = __ldcg(&p[t + 896]);

    float s = (((v0.x + v0.y) + (v0.z + v0.w))
            +  ((v1.x + v1.y) + (v1.z + v1.w)))
            + (((v2.x + v2.y) + (v2.z + v2.w))
            +  ((v3.x + v3.y) + (v3.z + v3.w)))
            + (((v4.x + v4.y) + (v4.z + v4.w))
            +  ((v5.x + v5.y) + (v5.z + v5.w)))
            + (((v6.x + v6.y) + (v6.z + v6.w))
            +  ((v7.x + v7.y) + (v7.z + v7.w)));

    #pragma unroll
    for (int off = 16; off > 0; off >>= 1)
        s += __shfl_down_sync(0xFFFFFFFFu, s, off);

    __shared__ float sh[4];
    const int wid = t >> 5;
    const int lid = t & 31;
    if (lid == 0) sh[wid] = s;
    __syncthreads();

    if (t == 0)
        out[0] = (sh[0] + sh[1]) + (sh[2] + sh[3]);
}

extern "C" void kernel_launch(void* const* d_in, const int* in_sizes, int n_in,
                              void* d_out, int out_size)
{
    const float* f     = (const float*)d_in[0];
    const float* label = (const float*)d_in[1];
    const int*   idx1  = (const int*)d_in[2];
    const int*   idx2  = (const int*)d_in[3];
    float* out = (float*)d_out;

    triplet_rows_kernel<<<GRID, 256>>>(f, label, idx1, idx2);

    cudaLaunchConfig_t cfg = {};
    cfg.gridDim  = dim3(1, 1, 1);
    cfg.blockDim = dim3(128, 1, 1);
    cfg.dynamicSmemBytes = 0;
    cudaLaunchAttribute attr[1];
    attr[0].id = cudaLaunchAttributeProgrammaticStreamSerialization;
    attr[0].val.programmaticStreamSerializationAllowed = 1;
    cfg.attrs = attr;
    cfg.numAttrs = 1;
    cudaLaunchKernelEx(&cfg, reduce_kernel, out);
}

// round 16
// speedup vs baseline: 1.1109x; 1.1109x over previous
#include <cuda_runtime.h>

#define BATCH 4096
#define DIM   4096
#define MARGIN 0.5f
#define GRID  1184   // 148 SMs x 8 CTAs -> exactly one wave, persistent

// scratch for per-row hinge losses (allocation-free rule: __device__ global)
__device__ float g_partial[BATCH];

// ---------------------------------------------------------------------------
// Kernel 1: persistent single-wave grid (measured champion: 18.53us).
// Each CTA handles rows cta, cta+GRID, ... with the proven 32-reg float4
// inner loop (occ ~89%, LTS at measured chip cap). Partials stored per row
// with stcg (straight to L2). launch_dependents at loop exit.
// ---------------------------------------------------------------------------
__global__ __launch_bounds__(256, 8)
void triplet_rows_kernel(const float* __restrict__ f,
                         const float* __restrict__ label,
                         const int*   __restrict__ idx1,
                         const int*   __restrict__ idx2)
{
    const int t   = threadIdx.x;
    const int wid = t >> 5;
    const int lid = t & 31;

    __shared__ float sh1[8], sh2[8];

    for (int i = blockIdx.x; i < BATCH; i += GRID) {
        const int j1 = __ldg(&idx1[i]);
        const int j2 = __ldg(&idx2[i]);

        const float4* __restrict__ a  = (const float4*)(f + (size_t)i  * DIM);
        const float4* __restrict__ b1 = (const float4*)(f + (size_t)j1 * DIM);
        const float4* __restrict__ b2 = (const float4*)(f + (size_t)j2 * DIM);

        float s1 = 0.0f, s2 = 0.0f;

        #pragma unroll
        for (int k = 0; k < 4; k++) {
            const int idx = t + k * 256;
            const float4 av = __ldg(&a[idx]);
            const float4 v1 = __ldg(&b1[idx]);
            const float4 v2 = __ldg(&b2[idx]);
            float d;
            d = av.x - v1.x; s1 = fmaf(d, d, s1);
            d = av.y - v1.y; s1 = fmaf(d, d, s1);
            d = av.z - v1.z; s1 = fmaf(d, d, s1);
            d = av.w - v1.w; s1 = fmaf(d, d, s1);
            d = av.x - v2.x; s2 = fmaf(d, d, s2);
            d = av.y - v2.y; s2 = fmaf(d, d, s2);
            d = av.z - v2.z; s2 = fmaf(d, d, s2);
            d = av.w - v2.w; s2 = fmaf(d, d, s2);
        }

        #pragma unroll
        for (int off = 16; off > 0; off >>= 1) {
            s1 += __shfl_down_sync(0xFFFFFFFFu, s1, off);
            s2 += __shfl_down_sync(0xFFFFFFFFu, s2, off);
        }

        if (lid == 0) { sh1[wid] = s1; sh2[wid] = s2; }
        __syncthreads();

        if (t == 0) {
            float t1 = 0.0f, t2 = 0.0f;
            #pragma unroll
            for (int w = 0; w < 8; w++) { t1 += sh1[w]; t2 += sh2[w]; }

            const float l  = __ldg(&label[i]);
            const float l1 = __ldg(&label[j1]);
            const float l2 = __ldg(&label[j2]);
            const float d1 = fabsf(l - l1);
            const float d2 = fabsf(l - l2);
            const bool cond = (d1 >= d2);   // true -> idx2 is the near sample

            const float a2n    = cond ? t2 : t1;
            const float a2f    = cond ? t1 : t2;
            const float near_l = cond ? l2 : l1;
            const float far_l  = cond ? l1 : l2;

            const float dn = l - near_l;
            const float df = l - far_l;
            const float alpha = df * df - dn * dn;
            __stcg(&g_partial[i], fmaxf(a2n - a2f + alpha * MARGIN, 0.0f));
        }
        __syncthreads();   // protect sh1/sh2 reuse across row iterations
    }

    // Let the dependent reduce start its launch; its griddepcontrol.wait
    // still blocks until this grid fully completes + flushes.
    asm volatile("griddepcontrol.launch_dependents;");
}

// ---------------------------------------------------------------------------
// Kernel 2: PDL-launched reduce. Waits for predecessor completion (flush),
// then deterministic fixed-order sum of 4096 partials via L2.
// ---------------------------------------------------------------------------
__global__ __launch_bounds__(128, 1)
void reduce_kernel(float* __restrict__ out)
{
    asm volatile("griddepcontrol.wait;");

    const int t = threadIdx.x;
    const float4* p = (const float4*)g_partial;  // 1024 float4

    const float4 v0 = __ldcg(&p[t]);
    const float4 v1 = __ldcg(&p[t + 128]);
    const float4 v2 = __ldcg(&p[t + 256]);
    const float4 v3 = __ldcg(&p[t + 384]);
    const float4 v4 = __ldcg(&p[t + 512]);
    const float4 v5 = __ldcg(&p[t + 640]);
    const float4 v6 = __ldcg(&p[t + 768]);
    const float4 v7 = __ldcg(&p[t + 896]);

    float s = (((v0.x + v0.y) + (v0.z + v0.w))
            +  ((v1.x + v1.y) + (v1.z + v1.w)))
            + (((v2.x + v2.y) + (v2.z + v2.w))
            +  ((v3.x + v3.y) + (v3.z + v3.w)))
            + (((v4.x + v4.y) + (v4.z + v4.w))
            +  ((v5.x + v5.y) + (v5.z + v5.w)))
            + (((v6.x + v6.y) + (v6.z + v6.w))
            +  ((v7.x + v7.y) + (v7.z + v7.w)));

    #pragma unroll
    for (int off = 16; off > 0; off >>= 1)
        s += __shfl_down_sync(0xFFFFFFFFu, s, off);

    __shared__ float sh[4];
    const int wid = t >> 5;
    const int lid = t & 31;
    if (lid == 0) sh[wid] = s;
    __syncthreads();

    if (t == 0)
        out[0] = (sh[0] + sh[1]) + (sh[2] + sh[3]);
}

extern "C" void kernel_launch(void* const* d_in, const int* in_sizes, int n_in,
                              void* d_out, int out_size)
{
    const float* f     = (const float*)d_in[0];
    const float* label = (const float*)d_in[1];
    const int*   idx1  = (const int*)d_in[2];
    const int*   idx2  = (const int*)d_in[3];
    float* out = (float*)d_out;

    triplet_rows_kernel<<<GRID, 256>>>(f, label, idx1, idx2);

    cudaLaunchConfig_t cfg = {};
    cfg.gridDim  = dim3(1, 1, 1);
    cfg.blockDim = dim3(128, 1, 1);
    cfg.dynamicSmemBytes = 0;
    cudaLaunchAttribute attr[1];
    attr[0].id = cudaLaunchAttributeProgrammaticStreamSerialization;
    attr[0].val.programmaticStreamSerializationAllowed = 1;
    cfg.attrs = attr;
    cfg.numAttrs = 1;
    cudaLaunchKernelEx(&cfg, reduce_kernel, out);
}

// round 17
// speedup vs baseline: 1.1416x; 1.0276x over previous
#include <cuda_runtime.h>

#define BATCH 4096
#define DIM   4096
#define MARGIN 0.5f
#define GRID  1184   // 148 SMs x 8 CTAs -> exactly one wave, persistent

// scratch for per-row hinge losses (allocation-free rule: __device__ global)
__device__ float g_partial[BATCH];

// ---------------------------------------------------------------------------
// Kernel 1: champion persistent single-wave grid, with the per-iteration
// trailing __syncthreads removed via parity double-buffered smem. One barrier
// per row instead of two; t0's epilogue overlaps the other warps' next-row
// loads.
// ---------------------------------------------------------------------------
__global__ __launch_bounds__(256, 8)
void triplet_rows_kernel(const float* __restrict__ f,
                         const float* __restrict__ label,
                         const int*   __restrict__ idx1,
                         const int*   __restrict__ idx2)
{
    const int t   = threadIdx.x;
    const int wid = t >> 5;
    const int lid = t & 31;

    __shared__ float sh1[2][8], sh2[2][8];   // parity double buffer

    int p = 0;
    for (int i = blockIdx.x; i < BATCH; i += GRID, p ^= 1) {
        const int j1 = __ldg(&idx1[i]);
        const int j2 = __ldg(&idx2[i]);

        const float4* __restrict__ a  = (const float4*)(f + (size_t)i  * DIM);
        const float4* __restrict__ b1 = (const float4*)(f + (size_t)j1 * DIM);
        const float4* __restrict__ b2 = (const float4*)(f + (size_t)j2 * DIM);

        float s1 = 0.0f, s2 = 0.0f;

        #pragma unroll
        for (int k = 0; k < 4; k++) {
            const int idx = t + k * 256;
            const float4 av = __ldg(&a[idx]);
            const float4 v1 = __ldg(&b1[idx]);
            const float4 v2 = __ldg(&b2[idx]);
            float d;
            d = av.x - v1.x; s1 = fmaf(d, d, s1);
            d = av.y - v1.y; s1 = fmaf(d, d, s1);
            d = av.z - v1.z; s1 = fmaf(d, d, s1);
            d = av.w - v1.w; s1 = fmaf(d, d, s1);
            d = av.x - v2.x; s2 = fmaf(d, d, s2);
            d = av.y - v2.y; s2 = fmaf(d, d, s2);
            d = av.z - v2.z; s2 = fmaf(d, d, s2);
            d = av.w - v2.w; s2 = fmaf(d, d, s2);
        }

        #pragma unroll
        for (int off = 16; off > 0; off >>= 1) {
            s1 += __shfl_down_sync(0xFFFFFFFFu, s1, off);
            s2 += __shfl_down_sync(0xFFFFFFFFu, s2, off);
        }

        if (lid == 0) { sh1[p][wid] = s1; sh2[p][wid] = s2; }
        __syncthreads();   // single barrier per row

        if (t == 0) {
            float t1 = 0.0f, t2 = 0.0f;
            #pragma unroll
            for (int w = 0; w < 8; w++) { t1 += sh1[p][w]; t2 += sh2[p][w]; }

            const float l  = __ldg(&label[i]);
            const float l1 = __ldg(&label[j1]);
            const float l2 = __ldg(&label[j2]);
            const float d1 = fabsf(l - l1);
            const float d2 = fabsf(l - l2);
            const bool cond = (d1 >= d2);   // true -> idx2 is the near sample

            const float a2n    = cond ? t2 : t1;
            const float a2f    = cond ? t1 : t2;
            const float near_l = cond ? l2 : l1;
            const float far_l  = cond ? l1 : l2;

            const float dn = l - near_l;
            const float df = l - far_l;
            const float alpha = df * df - dn * dn;
            __stcg(&g_partial[i], fmaxf(a2n - a2f + alpha * MARGIN, 0.0f));
        }
        // no trailing barrier: next iteration writes the other parity buffer;
        // t0's reads of sh[p] complete before it arrives at the next barrier.
    }

    // Let the dependent reduce start its launch; its griddepcontrol.wait
    // still blocks until this grid fully completes + flushes.
    asm volatile("griddepcontrol.launch_dependents;");
}

// ---------------------------------------------------------------------------
// Kernel 2: PDL-launched reduce. Waits for predecessor completion (flush),
// then deterministic fixed-order sum of 4096 partials via L2.
// ---------------------------------------------------------------------------
__global__ __launch_bounds__(128, 1)
void reduce_kernel(float* __restrict__ out)
{
    asm volatile("griddepcontrol.wait;");

    const int t = threadIdx.x;
    const float4* p = (const float4*)g_partial;  // 1024 float4

    const float4 v0 = __ldcg(&p[t]);
    const float4 v1 = __ldcg(&p[t + 128]);
    const float4 v2 = __ldcg(&p[t + 256]);
    const float4 v3 = __ldcg(&p[t + 384]);
    const float4 v4 = __ldcg(&p[t + 512]);
    const float4 v5 = __ldcg(&p[t + 640]);
    const float4 v6 = __ldcg(&p[t + 768]);
    const float4 v7 = __ldcg(&p[t + 896]);

    float s = (((v0.x + v0.y) + (v0.z + v0.w))
            +  ((v1.x + v1.y) + (v1.z + v1.w)))
            + (((v2.x + v2.y) + (v2.z + v2.w))
            +  ((v3.x + v3.y) + (v3.z + v3.w)))
            + (((v4.x + v4.y) + (v4.z + v4.w))
            +  ((v5.x + v5.y) + (v5.z + v5.w)))
            + (((v6.x + v6.y) + (v6.z + v6.w))
            +  ((v7.x + v7.y) + (v7.z + v7.w)));

    #pragma unroll
    for (int off = 16; off > 0; off >>= 1)
        s += __shfl_down_sync(0xFFFFFFFFu, s, off);

    __shared__ float sh[4];
    const int wid = t >> 5;
    const int lid = t & 31;
    if (lid == 0) sh[wid] = s;
    __syncthreads();

    if (t == 0)
        out[0] = (sh[0] + sh[1]) + (sh[2] + sh[3]);
}

extern "C" void kernel_launch(void* const* d_in, const int* in_sizes, int n_in,
                              void* d_out, int out_size)
{
    const float* f     = (const float*)d_in[0];
    const float* label = (const float*)d_in[1];
    const int*   idx1  = (const int*)d_in[2];
    const int*   idx2  = (const int*)d_in[3];
    float* out = (float*)d_out;

    triplet_rows_kernel<<<GRID, 256>>>(f, label, idx1, idx2);

    cudaLaunchConfig_t cfg = {};
    cfg.gridDim  = dim3(1, 1, 1);
    cfg.blockDim = dim3(128, 1, 1);
    cfg.dynamicSmemBytes = 0;
    cudaLaunchAttribute attr[1];
    attr[0].id = cudaLaunchAttributeProgrammaticStreamSerialization;
    attr[0].val.programmaticStreamSerializationAllowed = 1;
    cfg.attrs = attr;
    cfg.numAttrs = 1;
    cudaLaunchKernelEx(&cfg, reduce_kernel, out);
}